// round 17
// baseline (speedup 1.0000x reference)
#include <cuda_runtime.h>
#include <cuda_bf16.h>
#include <cstdint>

typedef unsigned int u32;

#define LSEQ 2048
#define DIMV 32
#define CHK 64
#define NCH 32
#define THREADS 256
#define NPAIRS 496
#define OUTW 528

#define STAGE 16384                 // A tile (8KB) + B tile (8KB)
#define BOFF 8192
#define SMEMSZ (2 * STAGE)          // 32768 (2-stage ring; reused as C[64][66] after)

#define NB_SYNC(id)   asm volatile("bar.sync %0, 256;" ::"r"(id) : "memory")
#define NB_ARRIVE(id) asm volatile("bar.arrive %0, 256;" ::"r"(id) : "memory")

__device__ __forceinline__ u32 smem_u32(const void* p) {
    u32 a;
    asm("{ .reg .u64 t; cvta.to.shared.u64 t, %1; cvt.u32.u64 %0, t; }" : "=r"(a) : "l"(p));
    return a;
}
__device__ __forceinline__ u32 cvtpack(float lo, float hi) {   // low half = lo
    u32 r;
    asm("cvt.rn.bf16x2.f32 %0, %1, %2;" : "=r"(r) : "f"(hi), "f"(lo));
    return r;
}
__device__ __forceinline__ void sts128(u32 a, u32 x0, u32 x1, u32 x2, u32 x3) {
    asm volatile("st.shared.v4.b32 [%0], {%1,%2,%3,%4};"
                 ::"r"(a), "r"(x0), "r"(x1), "r"(x2), "r"(x3));
}
__device__ __forceinline__ void ldsm4(u32 addr, u32* r) {
    asm volatile("ldmatrix.sync.aligned.m8n8.x4.shared.b16 {%0,%1,%2,%3}, [%4];"
                 : "=r"(r[0]), "=r"(r[1]), "=r"(r[2]), "=r"(r[3]) : "r"(addr));
}
__device__ __forceinline__ void mma16816(float* d, const u32* a, u32 b0, u32 b1) {
    asm volatile(
        "mma.sync.aligned.m16n8k16.row.col.f32.bf16.bf16.f32 "
        "{%0,%1,%2,%3}, {%4,%5,%6,%7}, {%8,%9}, {%0,%1,%2,%3};"
        : "+f"(d[0]), "+f"(d[1]), "+f"(d[2]), "+f"(d[3])
        : "r"(a[0]), "r"(a[1]), "r"(a[2]), "r"(a[3]), "r"(b0), "r"(b1));
}

__global__ __launch_bounds__(THREADS, 3) void logsig_ws(const float* __restrict__ x,
                                                        float* __restrict__ out) {
    __shared__ __align__(128) char smem[SMEMSZ];
    __shared__ float x0s[DIMV], l1s[DIMV];

    const int b = blockIdx.x, tid = threadIdx.x, w = tid >> 5, lane = tid & 31;
    const float* gx = x + (size_t)b * LSEQ * DIMV;
    const u32 sbase = smem_u32(smem);

    float acc[8][4];                 // consumers only (producers leave it dead)
#pragma unroll
    for (int i = 0; i < 8; i++)
#pragma unroll
        for (int r = 0; r < 4; r++) acc[i][r] = 0.f;

    if (w < 4) {
        // ================= PRODUCER (warps 0-3) =================
        const int pw = w;                        // k-block 16*pw .. 16*pw+16
        // load rows 16pw..16pw+16 (dim = lane) of chunk c
        auto loadv = [&](float* v, int c) {
            const float* p = gx + (size_t)(c * CHK + 16 * pw) * DIMV + lane;
#pragma unroll
            for (int j = 0; j < 17; j++) {
                bool ok = (c * CHK + 16 * pw + j) < LSEQ;     // only global row 2048 fails
                v[j] = ok ? __ldg(p + j * DIMV) : 0.0f;
            }
        };

        float v[17];
        loadv(v, 0);

#pragma unroll 1
        for (int c = 0; c < NCH; c++) {
            const int s = c & 1;
            NB_SYNC(3 + s);                      // wait: stage s free (primed by consumers)

            const u32 buf = sbase + (u32)s * STAGE;
            // convert 17 f32 -> bf16 hi + residual
            u32 h2[17];
            float res[17];
#pragma unroll
            for (int j = 0; j < 17; j++) {
                h2[j] = cvtpack(v[j], v[j]);
                res[j] = v[j] - __uint_as_float(h2[j] & 0xFFFF0000u);
            }
            u32 ah[8], al[8], bh[8], bl[8];
#pragma unroll
            for (int i = 0; i < 8; i++) {
                ah[i] = __byte_perm(h2[2 * i], h2[2 * i + 1], 0x7632);
                al[i] = cvtpack(res[2 * i], res[2 * i + 1]);
                bh[i] = __byte_perm(h2[2 * i + 1], h2[2 * i + 2], 0x7632);
                bl[i] = cvtpack(res[2 * i + 1], res[2 * i + 2]);
            }
            // STS: rows = dim (A: lane hi / lane+32 lo), units 2pw+t swizzled by lane&7
#pragma unroll
            for (int t = 0; t < 2; t++) {
                const u32 off = (u32)lane * 128u + (((u32)(2 * pw + t) ^ (u32)(lane & 7)) << 4);
                sts128(buf + off,                 ah[4 * t], ah[4 * t + 1], ah[4 * t + 2], ah[4 * t + 3]);
                sts128(buf + off + 4096u,         al[4 * t], al[4 * t + 1], al[4 * t + 2], al[4 * t + 3]);
                sts128(buf + off + BOFF,          bh[4 * t], bh[4 * t + 1], bh[4 * t + 2], bh[4 * t + 3]);
                sts128(buf + off + BOFF + 4096u,  bl[4 * t], bl[4 * t + 1], bl[4 * t + 2], bl[4 * t + 3]);
            }
            asm volatile("fence.acq_rel.cta;" ::: "memory");  // order STS before arrive
            NB_ARRIVE(1 + s);                    // signal: stage s ready

            if (c + 1 < NCH) loadv(v, c + 1);    // overlap next chunk's LDG with consumers
        }
    } else {
        // ================= CONSUMER (warps 4-7, one per SMSP) =================
        const int cw = w - 4, mh = cw & 1, nh = cw >> 1;
        NB_ARRIVE(3);                            // prime: both stages initially free
        NB_ARRIVE(4);

        const int rla = lane & 15, khl = lane >> 4;
#pragma unroll 1
        for (int c = 0; c < NCH; c++) {
            const int s = c & 1;
            NB_SYNC(1 + s);                      // wait: stage s ready (acquire)

            const u32 buf = sbase + (u32)s * STAGE;
#pragma unroll
            for (int qi = 0; qi < 4; qi++) {     // full k64: 4 x k16
                const u32 u = (u32)(qi * 2 + khl);
                u32 afr[2][4], bfr[2][4];
#pragma unroll
                for (int tm = 0; tm < 2; tm++) {
                    u32 row = (u32)(mh * 32 + tm * 16 + rla);
                    ldsm4(buf + row * 128u + ((u ^ (row & 7u)) << 4), afr[tm]);
                }
#pragma unroll
                for (int tn = 0; tn < 2; tn++) {
                    u32 row = (u32)(nh * 32 + tn * 16 + rla);
                    ldsm4(buf + BOFF + row * 128u + ((u ^ (row & 7u)) << 4), bfr[tn]);
                }
#pragma unroll
                for (int tm = 0; tm < 2; tm++)
#pragma unroll
                    for (int tn = 0; tn < 2; tn++) {
                        mma16816(acc[tm * 4 + tn * 2 + 0], afr[tm], bfr[tn][0], bfr[tn][2]);
                        mma16816(acc[tm * 4 + tn * 2 + 1], afr[tm], bfr[tn][1], bfr[tn][3]);
                    }
            }
            NB_ARRIVE(3 + s);                    // mma issue forces ldsm done -> stage free
        }
    }

    __syncthreads();                             // everyone past loops; tile smem dead

    // ---- consumers hold full-k sums: write C[64][66] directly ----
    float* C = (float*)smem;
    if (w >= 4) {
        const int cw = w - 4, mh = cw & 1, nh = cw >> 1;
#pragma unroll
        for (int t = 0; t < 8; t++) {
            int tm = t >> 2, tn8 = t & 3;
#pragma unroll
            for (int r = 0; r < 4; r++) {
                int m = mh * 32 + tm * 16 + (lane >> 2) + (r >> 1) * 8;
                int n = nh * 32 + tn8 * 8 + (lane & 3) * 2 + (r & 1);
                C[m * 66 + n] = acc[t][r];
            }
        }
    }
    if (tid < DIMV) {
        float x0 = gx[tid];
        float l1 = gx[(size_t)(LSEQ - 1) * DIMV + tid] - x0;
        x0s[tid] = x0;
        l1s[tid] = l1;
        out[(size_t)b * OUTW + tid] = l1;        // level1
    }
    __syncthreads();

    // ---- areas: combine hi/lo blocks, antisymmetrize, correct, emit ----
#pragma unroll 1
    for (int p = tid; p < NPAIRS; p += THREADS) {
        float f = (63.0f - sqrtf((float)(3969 - 8 * p))) * 0.5f;
        int i = (int)f;
        int base = i * (63 - i) / 2;
        if (base > p) { i--; base = i * (63 - i) / 2; }
        else { int nb = (i + 1) * (62 - i) / 2; if (nb <= p) { i++; base = nb; } }
        int j = i + 1 + (p - base);
        float Cij = C[i * 66 + j] + C[i * 66 + j + 32]
                  + C[(i + 32) * 66 + j] + C[(i + 32) * 66 + j + 32];
        float Cji = C[j * 66 + i] + C[j * 66 + i + 32]
                  + C[(j + 32) * 66 + i] + C[(j + 32) * 66 + i + 32];
        out[(size_t)b * OUTW + DIMV + p] =
            0.5f * ((Cij - Cji) - x0s[i] * l1s[j] + x0s[j] * l1s[i]);
    }
}

extern "C" void kernel_launch(void* const* d_in, const int* in_sizes, int n_in,
                              void* d_out, int out_size) {
    const float* x = (const float*)d_in[0];
    float* out = (float*)d_out;
    const int B = in_sizes[0] / (LSEQ * DIMV);   // 512
    logsig_ws<<<B, THREADS>>>(x, out);
}